// round 5
// baseline (speedup 1.0000x reference)
#include <cuda_runtime.h>
#include <cuda_bf16.h>
#include <cstdint>

// Problem constants
#define B_   16
#define T_   2048
#define DIN  1024
#define DPRJ 512
#define DOUT 1024
#define LORD 20
#define MROWS (B_ * T_)          // 32768

// Scratch (allocation-free: __device__ globals)
__device__ float g_x[(size_t)MROWS * DPRJ];   // x = input @ W_lin   [M, 512]
__device__ float g_m[(size_t)MROWS * DPRJ];   // m = conv(x) + x     [M, 512]

__device__ __forceinline__ float4 ld4(const float* p) {
    return *reinterpret_cast<const float4*>(p);
}

// ---------------------------------------------------------------------------
// SGEMM: C[M,N] = A[M,K] * B[K,N]  (+ bias, relu if RELU)
// BM=BN=128, BK=8, TM=TN=8, 256 threads.
// ---------------------------------------------------------------------------
template <bool RELU>
__global__ __launch_bounds__(256, 2)
void sgemm128(int M, int N, int K,
              const float* __restrict__ A,
              const float* __restrict__ Bm,
              const float* __restrict__ bias,
              float* __restrict__ C)
{
    constexpr int BM = 128, BN = 128, BK = 8, TM = 8, TN = 8;
    __shared__ float As[BK * BM];   // transposed tile
    __shared__ float Bs[BK * BN];

    const int tid  = threadIdx.x;
    const int cRow = blockIdx.y;
    const int cCol = blockIdx.x;

    const float* Ap = A + (size_t)cRow * BM * K;
    const float* Bp = Bm + (size_t)cCol * BN;

    const int innerRowA = tid >> 1;          // 0..127
    const int innerColA = (tid & 1) * 4;     // 0 or 4
    const int innerRowB = tid >> 5;          // 0..7
    const int innerColB = (tid & 31) * 4;    // 0..124

    const int threadCol = tid & 15;          // 0..15
    const int threadRow = tid >> 4;          // 0..15

    float acc[TM][TN] = {};
    float regM[TM], regN[TN];

    for (int k0 = 0; k0 < K; k0 += BK) {
        float4 a = ld4(Ap + (size_t)innerRowA * K + innerColA);
        As[(innerColA + 0) * BM + innerRowA] = a.x;
        As[(innerColA + 1) * BM + innerRowA] = a.y;
        As[(innerColA + 2) * BM + innerRowA] = a.z;
        As[(innerColA + 3) * BM + innerRowA] = a.w;
        *reinterpret_cast<float4*>(&Bs[innerRowB * BN + innerColB]) =
            ld4(Bp + (size_t)innerRowB * N + innerColB);
        __syncthreads();
        Ap += BK;
        Bp += (size_t)BK * N;

        #pragma unroll
        for (int k = 0; k < BK; k++) {
            #pragma unroll
            for (int i = 0; i < TM; i++) regM[i] = As[k * BM + threadRow * TM + i];
            #pragma unroll
            for (int j = 0; j < TN; j++) regN[j] = Bs[k * BN + threadCol * TN + j];
            #pragma unroll
            for (int i = 0; i < TM; i++)
                #pragma unroll
                for (int j = 0; j < TN; j++)
                    acc[i][j] += regM[i] * regN[j];
        }
        __syncthreads();
    }

    // Epilogue
    float breg[TN];
    if (RELU) {
        #pragma unroll
        for (int j = 0; j < TN; j++)
            breg[j] = bias[cCol * BN + threadCol * TN + j];
    }
    #pragma unroll
    for (int i = 0; i < TM; i++) {
        const int row = cRow * BM + threadRow * TM + i;
        float* crow = C + (size_t)row * N + cCol * BN + threadCol * TN;
        #pragma unroll
        for (int j = 0; j < TN; j += 4) {
            float4 v;
            v.x = acc[i][j + 0]; v.y = acc[i][j + 1];
            v.z = acc[i][j + 2]; v.w = acc[i][j + 3];
            if (RELU) {
                v.x = fmaxf(v.x + breg[j + 0], 0.f);
                v.y = fmaxf(v.y + breg[j + 1], 0.f);
                v.z = fmaxf(v.z + breg[j + 2], 0.f);
                v.w = fmaxf(v.w + breg[j + 3], 0.f);
            }
            *reinterpret_cast<float4*>(crow + j) = v;
        }
    }
}

// ---------------------------------------------------------------------------
// Depthwise causal conv (L=20) + residual.
// x layout: [B*T, P] row-major. m same. in_cache: [B, P, 19]. conv_w: [P, 20].
// Each thread owns one p, walks TCHUNK timesteps with a 19-register window.
// ---------------------------------------------------------------------------
#define TCHUNK 128

__global__ __launch_bounds__(256)
void conv_residual_kernel(const float* __restrict__ x,
                          const float* __restrict__ in_cache,
                          const float* __restrict__ conv_w,
                          float* __restrict__ m)
{
    const int p  = blockIdx.x * 256 + threadIdx.x;   // 0..511
    const int b  = blockIdx.z;
    const int t0 = blockIdx.y * TCHUNK;

    float w[LORD];
    #pragma unroll
    for (int l = 0; l < LORD; l++) w[l] = conv_w[p * LORD + l];

    // win[i] = v[t0 - 19 + i], i = 0..18; v[j] = x[b,j,p] for j>=0 else in_cache
    float win[LORD - 1];
    #pragma unroll
    for (int i = 0; i < LORD - 1; i++) {
        const int j = t0 - (LORD - 1) + i;
        if (j >= 0)
            win[i] = x[((size_t)b * T_ + j) * DPRJ + p];
        else
            win[i] = in_cache[((size_t)b * DPRJ + p) * (LORD - 1) + (j + LORD - 1)];
    }

    const float* xrow = x + ((size_t)b * T_ + t0) * DPRJ + p;
    float*       mrow = m + ((size_t)b * T_ + t0) * DPRJ + p;

    for (int t = 0; t < TCHUNK; t++) {
        const float xv = xrow[(size_t)t * DPRJ];
        float acc = fmaf(w[LORD - 1], xv, xv);     // conv tap l=19 + residual
        #pragma unroll
        for (int l = 0; l < LORD - 1; l++)
            acc = fmaf(w[l], win[l], acc);
        mrow[(size_t)t * DPRJ] = acc;
        #pragma unroll
        for (int i = 0; i < LORD - 2; i++) win[i] = win[i + 1];
        win[LORD - 2] = xv;
    }
}

// ---------------------------------------------------------------------------
// out_cache[b,p,i] = x[b, T-19+i, p]
// ---------------------------------------------------------------------------
__global__ void cache_kernel(const float* __restrict__ x,
                             float* __restrict__ out_cache)
{
    const int idx = blockIdx.x * blockDim.x + threadIdx.x;
    const int total = B_ * DPRJ * (LORD - 1);
    if (idx >= total) return;
    const int i = idx % (LORD - 1);
    const int p = (idx / (LORD - 1)) % DPRJ;
    const int b = idx / ((LORD - 1) * DPRJ);
    out_cache[idx] = x[((size_t)b * T_ + (T_ - (LORD - 1) + i)) * DPRJ + p];
}

// ---------------------------------------------------------------------------
extern "C" void kernel_launch(void* const* d_in, const int* in_sizes, int n_in,
                              void* d_out, int out_size)
{
    const float* input    = (const float*)d_in[0];  // [16, 2048, 1024]
    const float* in_cache = (const float*)d_in[1];  // [16, 512, 19]
    const float* W_lin    = (const float*)d_in[2];  // [1024, 512]
    const float* conv_w   = (const float*)d_in[3];  // [512, 20]
    const float* W_aff    = (const float*)d_in[4];  // [512, 1024]
    const float* b_aff    = (const float*)d_in[5];  // [1024]

    float* out       = (float*)d_out;                        // [16,2048,1024]
    float* out_cache = out + (size_t)B_ * T_ * DOUT;         // [16,512,19]

    float* xbuf; float* mbuf;
    cudaGetSymbolAddress((void**)&xbuf, g_x);
    cudaGetSymbolAddress((void**)&mbuf, g_m);

    // 1) x = input @ W_lin      M=32768, N=512, K=1024
    {
        dim3 grid(DPRJ / 128, MROWS / 128);
        sgemm128<false><<<grid, 256>>>(MROWS, DPRJ, DIN, input, W_lin, nullptr, xbuf);
    }

    // 2) m = depthwise_conv(x) + x   (and out_cache)
    {
        dim3 grid(DPRJ / 256, T_ / TCHUNK, B_);
        conv_residual_kernel<<<grid, 256>>>(xbuf, in_cache, conv_w, mbuf);
        const int total = B_ * DPRJ * (LORD - 1);
        cache_kernel<<<(total + 255) / 256, 256>>>(xbuf, out_cache);
    }

    // 3) out = relu(m @ W_aff + b_aff)   M=32768, N=1024, K=512
    {
        dim3 grid(DOUT / 128, MROWS / 128);
        sgemm128<true><<<grid, 256>>>(MROWS, DOUT, DPRJ, mbuf, W_aff, b_aff, out);
    }
}

// round 6
// speedup vs baseline: 1.0005x; 1.0005x over previous
#include <cuda_runtime.h>
#include <cuda_bf16.h>
#include <cstdint>

// Problem constants
#define B_   16
#define T_   2048
#define DIN  1024
#define DPRJ 512
#define DOUT 1024
#define LORD 20
#define MROWS (B_ * T_)          // 32768

// Scratch (allocation-free: __device__ globals)
__device__ float g_x[(size_t)MROWS * DPRJ];   // x = input @ W_lin   [M, 512]
__device__ float g_m[(size_t)MROWS * DPRJ];   // m = conv(x) + x     [M, 512]

__device__ __forceinline__ float4 ld4(const float* p) {
    return *reinterpret_cast<const float4*>(p);
}

// ---------------------------------------------------------------------------
// SGEMM: C[M,N] = A[M,K] * B[K,N]  (+ bias, relu if RELU)
// BM=BN=128, BK=8, TM=TN=8, 256 threads.
// ---------------------------------------------------------------------------
template <bool RELU>
__global__ __launch_bounds__(256, 2)
void sgemm128(int M, int N, int K,
              const float* __restrict__ A,
              const float* __restrict__ Bm,
              const float* __restrict__ bias,
              float* __restrict__ C)
{
    constexpr int BM = 128, BN = 128, BK = 8, TM = 8, TN = 8;
    __shared__ float As[BK * BM];   // transposed tile
    __shared__ float Bs[BK * BN];

    const int tid  = threadIdx.x;
    const int cRow = blockIdx.y;
    const int cCol = blockIdx.x;

    const float* Ap = A + (size_t)cRow * BM * K;
    const float* Bp = Bm + (size_t)cCol * BN;

    const int innerRowA = tid >> 1;          // 0..127
    const int innerColA = (tid & 1) * 4;     // 0 or 4
    const int innerRowB = tid >> 5;          // 0..7
    const int innerColB = (tid & 31) * 4;    // 0..124

    const int threadCol = tid & 15;          // 0..15
    const int threadRow = tid >> 4;          // 0..15

    float acc[TM][TN] = {};
    float regM[TM], regN[TN];

    for (int k0 = 0; k0 < K; k0 += BK) {
        float4 a = ld4(Ap + (size_t)innerRowA * K + innerColA);
        As[(innerColA + 0) * BM + innerRowA] = a.x;
        As[(innerColA + 1) * BM + innerRowA] = a.y;
        As[(innerColA + 2) * BM + innerRowA] = a.z;
        As[(innerColA + 3) * BM + innerRowA] = a.w;
        *reinterpret_cast<float4*>(&Bs[innerRowB * BN + innerColB]) =
            ld4(Bp + (size_t)innerRowB * N + innerColB);
        __syncthreads();
        Ap += BK;
        Bp += (size_t)BK * N;

        #pragma unroll
        for (int k = 0; k < BK; k++) {
            #pragma unroll
            for (int i = 0; i < TM; i++) regM[i] = As[k * BM + threadRow * TM + i];
            #pragma unroll
            for (int j = 0; j < TN; j++) regN[j] = Bs[k * BN + threadCol * TN + j];
            #pragma unroll
            for (int i = 0; i < TM; i++)
                #pragma unroll
                for (int j = 0; j < TN; j++)
                    acc[i][j] += regM[i] * regN[j];
        }
        __syncthreads();
    }

    // Epilogue
    float breg[TN];
    if (RELU) {
        #pragma unroll
        for (int j = 0; j < TN; j++)
            breg[j] = bias[cCol * BN + threadCol * TN + j];
    }
    #pragma unroll
    for (int i = 0; i < TM; i++) {
        const int row = cRow * BM + threadRow * TM + i;
        float* crow = C + (size_t)row * N + cCol * BN + threadCol * TN;
        #pragma unroll
        for (int j = 0; j < TN; j += 4) {
            float4 v;
            v.x = acc[i][j + 0]; v.y = acc[i][j + 1];
            v.z = acc[i][j + 2]; v.w = acc[i][j + 3];
            if (RELU) {
                v.x = fmaxf(v.x + breg[j + 0], 0.f);
                v.y = fmaxf(v.y + breg[j + 1], 0.f);
                v.z = fmaxf(v.z + breg[j + 2], 0.f);
                v.w = fmaxf(v.w + breg[j + 3], 0.f);
            }
            *reinterpret_cast<float4*>(crow + j) = v;
        }
    }
}

// ---------------------------------------------------------------------------
// Depthwise causal conv (L=20) + residual.
// x layout: [B*T, P] row-major. m same. in_cache: [B, P, 19]. conv_w: [P, 20].
// Each thread owns one p, walks TCHUNK timesteps with a 19-register window.
// ---------------------------------------------------------------------------
#define TCHUNK 128

__global__ __launch_bounds__(256)
void conv_residual_kernel(const float* __restrict__ x,
                          const float* __restrict__ in_cache,
                          const float* __restrict__ conv_w,
                          float* __restrict__ m)
{
    const int p  = blockIdx.x * 256 + threadIdx.x;   // 0..511
    const int b  = blockIdx.z;
    const int t0 = blockIdx.y * TCHUNK;

    float w[LORD];
    #pragma unroll
    for (int l = 0; l < LORD; l++) w[l] = conv_w[p * LORD + l];

    // win[i] = v[t0 - 19 + i], i = 0..18; v[j] = x[b,j,p] for j>=0 else in_cache
    float win[LORD - 1];
    #pragma unroll
    for (int i = 0; i < LORD - 1; i++) {
        const int j = t0 - (LORD - 1) + i;
        if (j >= 0)
            win[i] = x[((size_t)b * T_ + j) * DPRJ + p];
        else
            win[i] = in_cache[((size_t)b * DPRJ + p) * (LORD - 1) + (j + LORD - 1)];
    }

    const float* xrow = x + ((size_t)b * T_ + t0) * DPRJ + p;
    float*       mrow = m + ((size_t)b * T_ + t0) * DPRJ + p;

    for (int t = 0; t < TCHUNK; t++) {
        const float xv = xrow[(size_t)t * DPRJ];
        float acc = fmaf(w[LORD - 1], xv, xv);     // conv tap l=19 + residual
        #pragma unroll
        for (int l = 0; l < LORD - 1; l++)
            acc = fmaf(w[l], win[l], acc);
        mrow[(size_t)t * DPRJ] = acc;
        #pragma unroll
        for (int i = 0; i < LORD - 2; i++) win[i] = win[i + 1];
        win[LORD - 2] = xv;
    }
}

// ---------------------------------------------------------------------------
// out_cache[b,p,i] = x[b, T-19+i, p]
// ---------------------------------------------------------------------------
__global__ void cache_kernel(const float* __restrict__ x,
                             float* __restrict__ out_cache)
{
    const int idx = blockIdx.x * blockDim.x + threadIdx.x;
    const int total = B_ * DPRJ * (LORD - 1);
    if (idx >= total) return;
    const int i = idx % (LORD - 1);
    const int p = (idx / (LORD - 1)) % DPRJ;
    const int b = idx / ((LORD - 1) * DPRJ);
    out_cache[idx] = x[((size_t)b * T_ + (T_ - (LORD - 1) + i)) * DPRJ + p];
}

// ---------------------------------------------------------------------------
extern "C" void kernel_launch(void* const* d_in, const int* in_sizes, int n_in,
                              void* d_out, int out_size)
{
    const float* input    = (const float*)d_in[0];  // [16, 2048, 1024]
    const float* in_cache = (const float*)d_in[1];  // [16, 512, 19]
    const float* W_lin    = (const float*)d_in[2];  // [1024, 512]
    const float* conv_w   = (const float*)d_in[3];  // [512, 20]
    const float* W_aff    = (const float*)d_in[4];  // [512, 1024]
    const float* b_aff    = (const float*)d_in[5];  // [1024]

    float* out       = (float*)d_out;                        // [16,2048,1024]
    float* out_cache = out + (size_t)B_ * T_ * DOUT;         // [16,512,19]

    float* xbuf; float* mbuf;
    cudaGetSymbolAddress((void**)&xbuf, g_x);
    cudaGetSymbolAddress((void**)&mbuf, g_m);

    // 1) x = input @ W_lin      M=32768, N=512, K=1024
    {
        dim3 grid(DPRJ / 128, MROWS / 128);
        sgemm128<false><<<grid, 256>>>(MROWS, DPRJ, DIN, input, W_lin, nullptr, xbuf);
    }

    // 2) m = depthwise_conv(x) + x   (and out_cache)
    {
        dim3 grid(DPRJ / 256, T_ / TCHUNK, B_);
        conv_residual_kernel<<<grid, 256>>>(xbuf, in_cache, conv_w, mbuf);
        const int total = B_ * DPRJ * (LORD - 1);
        cache_kernel<<<(total + 255) / 256, 256>>>(xbuf, out_cache);
    }

    // 3) out = relu(m @ W_aff + b_aff)   M=32768, N=1024, K=512
    {
        dim3 grid(DOUT / 128, MROWS / 128);
        sgemm128<true><<<grid, 256>>>(MROWS, DOUT, DPRJ, mbuf, W_aff, b_aff, out);
    }
}

// round 9
// speedup vs baseline: 1.9524x; 1.9514x over previous
#include <cuda_runtime.h>
#include <cuda_bf16.h>
#include <cstdint>

// Problem constants
#define B_   16
#define T_   2048
#define DIN  1024
#define DPRJ 512
#define DOUT 1024
#define LORD 20
#define MROWS (B_ * T_)          // 32768

// ---------------------------------------------------------------------------
// Device scratch (allocation-free)
// ---------------------------------------------------------------------------
__device__ float g_x[(size_t)MROWS * DPRJ];   // x = input @ W_lin   [M, 512] fp32
__device__ float g_m[(size_t)MROWS * DPRJ];   // m = conv(x) + x     [M, 512] fp32
// Transposed, split weights: rows = N dim, K contiguous
__device__ __nv_bfloat16 g_b1h[(size_t)DPRJ * DIN];   // [512][1024]
__device__ __nv_bfloat16 g_b1l[(size_t)DPRJ * DIN];
__device__ __nv_bfloat16 g_b2h[(size_t)DOUT * DPRJ];  // [1024][512]
__device__ __nv_bfloat16 g_b2l[(size_t)DOUT * DPRJ];

__device__ __forceinline__ float4 ld4(const float* p) {
    return *reinterpret_cast<const float4*>(p);
}

__device__ __forceinline__ uint32_t smem_u32(const void* p) {
    uint32_t a;
    asm("{ .reg .u64 t; cvta.to.shared.u64 t, %1; cvt.u32.u64 %0, t; }"
        : "=r"(a) : "l"(p));
    return a;
}

// ldmatrix x4 (four 8x8 b16 matrices)
__device__ __forceinline__ void ldsm4(uint32_t* r, uint32_t addr) {
    asm volatile("ldmatrix.sync.aligned.m8n8.x4.shared.b16 {%0,%1,%2,%3}, [%4];"
                 : "=r"(r[0]), "=r"(r[1]), "=r"(r[2]), "=r"(r[3])
                 : "r"(addr));
}

// mma.sync m16n8k16 bf16 -> f32
__device__ __forceinline__ void mma_bf16(float* c, const uint32_t* a,
                                         uint32_t b0, uint32_t b1) {
    asm volatile(
        "mma.sync.aligned.m16n8k16.row.col.f32.bf16.bf16.f32 "
        "{%0,%1,%2,%3}, {%4,%5,%6,%7}, {%8,%9}, {%0,%1,%2,%3};"
        : "+f"(c[0]), "+f"(c[1]), "+f"(c[2]), "+f"(c[3])
        : "r"(a[0]), "r"(a[1]), "r"(a[2]), "r"(a[3]), "r"(b0), "r"(b1));
}

// ---------------------------------------------------------------------------
// Tensor-core GEMM via mma.sync: C[M,N] = A[M,K] * B^T  (bf16 3-term split)
// CTA 128x128, KC=32, 256 threads (8 warps, 2x4), warp tile 64x32.
// SMEM: per stage: Ah, Al, Bh, Bl each [128][40] bf16 (stride-40 padding).
// ---------------------------------------------------------------------------
#define KC        32
#define STR       40                      // padded row stride in elements
#define TEN_BYTES (128 * STR * 2)         // 10240 B per tensor
#define STG_BYTES (4 * TEN_BYTES)         // 40960 B per stage

template <bool RELU>
__global__ __launch_bounds__(256)
void gemm_mma(int M, int N, int K,
              const float* __restrict__ A,
              const __nv_bfloat16* __restrict__ Bhg_,
              const __nv_bfloat16* __restrict__ Blg_,
              const float* __restrict__ bias,
              float* __restrict__ C)
{
    extern __shared__ char smem_raw[];

    const int tid  = threadIdx.x;
    const int lane = tid & 31;
    const int wid  = tid >> 5;
    const int warpM = wid >> 2;           // 0..1
    const int warpN = wid & 3;            // 0..3
    const int nt = blockIdx.x;
    const int mt = blockIdx.y;
    const int NKC = K / KC;

    const float* Ag = A + (size_t)mt * 128 * K;
    const __nv_bfloat16* Bhg = Bhg_ + (size_t)nt * 128 * K;
    const __nv_bfloat16* Blg = Blg_ + (size_t)nt * 128 * K;

    float acc[4][4][4];
    #pragma unroll
    for (int i = 0; i < 4; i++)
        #pragma unroll
        for (int j = 0; j < 4; j++)
            #pragma unroll
            for (int q = 0; q < 4; q++) acc[i][j][q] = 0.f;

    // staging registers for next chunk
    float4 ra[4];
    uint4  rbh[2], rbl[2];

    const uint32_t sb = smem_u32(smem_raw);

    // ---- helpers (lambdas keep register reuse tight) ----
    auto load_regs = [&](int kc) {
        #pragma unroll
        for (int it = 0; it < 4; it++) {
            const int i  = tid + it * 256;       // 0..1023
            const int r  = i >> 3;               // 0..127
            const int c4 = i & 7;                // k = c4*4
            ra[it] = ld4(Ag + (size_t)r * K + kc * KC + c4 * 4);
        }
        #pragma unroll
        for (int it = 0; it < 2; it++) {
            const int i  = tid + it * 256;       // 0..511
            const int r  = i >> 2;               // 0..127
            const int c8 = i & 3;                // k = c8*8
            const size_t go = (size_t)r * K + kc * KC + c8 * 8;
            rbh[it] = *reinterpret_cast<const uint4*>(Bhg + go);
            rbl[it] = *reinterpret_cast<const uint4*>(Blg + go);
        }
    };

    auto store_regs = [&](int s) {
        char* st = smem_raw + s * STG_BYTES;
        #pragma unroll
        for (int it = 0; it < 4; it++) {
            const int i  = tid + it * 256;
            const int r  = i >> 3;
            const int c4 = i & 7;
            const float4 v = ra[it];
            __nv_bfloat16 hx = __float2bfloat16(v.x);
            __nv_bfloat16 hy = __float2bfloat16(v.y);
            __nv_bfloat16 hz = __float2bfloat16(v.z);
            __nv_bfloat16 hw = __float2bfloat16(v.w);
            __nv_bfloat16 lx = __float2bfloat16(v.x - __bfloat162float(hx));
            __nv_bfloat16 ly = __float2bfloat16(v.y - __bfloat162float(hy));
            __nv_bfloat16 lz = __float2bfloat16(v.z - __bfloat162float(hz));
            __nv_bfloat16 lw = __float2bfloat16(v.w - __bfloat162float(hw));
            uint2 hv, lv;
            hv.x = (uint32_t)__bfloat16_as_ushort(hx) | ((uint32_t)__bfloat16_as_ushort(hy) << 16);
            hv.y = (uint32_t)__bfloat16_as_ushort(hz) | ((uint32_t)__bfloat16_as_ushort(hw) << 16);
            lv.x = (uint32_t)__bfloat16_as_ushort(lx) | ((uint32_t)__bfloat16_as_ushort(ly) << 16);
            lv.y = (uint32_t)__bfloat16_as_ushort(lz) | ((uint32_t)__bfloat16_as_ushort(lw) << 16);
            const int off = (r * STR + c4 * 4) * 2;          // bytes
            *reinterpret_cast<uint2*>(st + off)             = hv;   // A_hi
            *reinterpret_cast<uint2*>(st + TEN_BYTES + off) = lv;   // A_lo
        }
        #pragma unroll
        for (int it = 0; it < 2; it++) {
            const int i  = tid + it * 256;
            const int r  = i >> 2;
            const int c8 = i & 3;
            const int off = (r * STR + c8 * 8) * 2;
            *reinterpret_cast<uint4*>(st + 2 * TEN_BYTES + off) = rbh[it];  // B_hi
            *reinterpret_cast<uint4*>(st + 3 * TEN_BYTES + off) = rbl[it];  // B_lo
        }
    };

    const int lr = lane & 15;
    const int lc = lane >> 4;

    auto compute = [&](int s) {
        const uint32_t sAh = sb + s * STG_BYTES;
        const uint32_t sAl = sAh + TEN_BYTES;
        const uint32_t sBh = sAh + 2 * TEN_BYTES;
        const uint32_t sBl = sAh + 3 * TEN_BYTES;
        #pragma unroll
        for (int ks = 0; ks < KC; ks += 16) {
            uint32_t ah[4][4], al[4][4], bh[2][4], bl[2][4];
            #pragma unroll
            for (int i = 0; i < 4; i++) {
                const uint32_t ao =
                    ((warpM * 64 + i * 16 + lr) * STR + ks + lc * 8) * 2;
                ldsm4(ah[i], sAh + ao);
                ldsm4(al[i], sAl + ao);
            }
            #pragma unroll
            for (int jj = 0; jj < 2; jj++) {
                const uint32_t bo =
                    ((warpN * 32 + jj * 16 + lr) * STR + ks + lc * 8) * 2;
                ldsm4(bh[jj], sBh + bo);
                ldsm4(bl[jj], sBl + bo);
            }
            #pragma unroll
            for (int i = 0; i < 4; i++) {
                #pragma unroll
                for (int j = 0; j < 4; j++) {
                    const int jj = j >> 1, sel = j & 1;
                    const uint32_t b0h = bh[jj][sel], b1h = bh[jj][sel + 2];
                    mma_bf16(acc[i][j], ah[i], b0h, b1h);                       // Ah*Bh
                    mma_bf16(acc[i][j], al[i], b0h, b1h);                       // Al*Bh
                    mma_bf16(acc[i][j], ah[i], bl[jj][sel], bl[jj][sel + 2]);   // Ah*Bl
                }
            }
        }
    };

    // ---- pipeline: register-staged double buffer ----
    load_regs(0);
    store_regs(0);
    __syncthreads();
    for (int kc = 0; kc < NKC; kc++) {
        if (kc + 1 < NKC) load_regs(kc + 1);     // LDGs overlap compute
        compute(kc & 1);
        if (kc + 1 < NKC) store_regs((kc + 1) & 1);
        __syncthreads();
    }

    // ---- epilogue ----
    #pragma unroll
    for (int i = 0; i < 4; i++) {
        const int row0 = mt * 128 + warpM * 64 + i * 16 + (lane >> 2);
        #pragma unroll
        for (int j = 0; j < 4; j++) {
            const int col = nt * 128 + warpN * 32 + j * 8 + (lane & 3) * 2;
            float2 v0, v1;
            v0.x = acc[i][j][0]; v0.y = acc[i][j][1];   // row0
            v1.x = acc[i][j][2]; v1.y = acc[i][j][3];   // row0 + 8
            if (RELU) {
                const float b0 = bias[col], b1 = bias[col + 1];
                v0.x = fmaxf(v0.x + b0, 0.f); v0.y = fmaxf(v0.y + b1, 0.f);
                v1.x = fmaxf(v1.x + b0, 0.f); v1.y = fmaxf(v1.y + b1, 0.f);
            }
            *reinterpret_cast<float2*>(C + (size_t)row0 * N + col)       = v0;
            *reinterpret_cast<float2*>(C + (size_t)(row0 + 8) * N + col) = v1;
        }
    }
}

// ---------------------------------------------------------------------------
// Weight prep: transpose + bf16 hi/lo split
// ---------------------------------------------------------------------------
__global__ void prep_w1(const float* __restrict__ W,   // W_lin [1024,512]
                        __nv_bfloat16* __restrict__ bh,
                        __nv_bfloat16* __restrict__ bl)
{
    const int idx = blockIdx.x * 256 + threadIdx.x;
    if (idx >= DPRJ * DIN) return;
    const int n = idx / DIN, k = idx % DIN;
    const float v = W[(size_t)k * DPRJ + n];
    const __nv_bfloat16 h = __float2bfloat16(v);
    bh[idx] = h;
    bl[idx] = __float2bfloat16(v - __bfloat162float(h));
}

__global__ void prep_w2(const float* __restrict__ W,   // W_aff [512,1024]
                        __nv_bfloat16* __restrict__ bh,
                        __nv_bfloat16* __restrict__ bl)
{
    const int idx = blockIdx.x * 256 + threadIdx.x;
    if (idx >= DOUT * DPRJ) return;
    const int o = idx / DPRJ, p = idx % DPRJ;
    const float v = W[(size_t)p * DOUT + o];
    const __nv_bfloat16 h = __float2bfloat16(v);
    bh[idx] = h;
    bl[idx] = __float2bfloat16(v - __bfloat162float(h));
}

// ---------------------------------------------------------------------------
// Depthwise causal conv (L=20) + residual (fp32 in/out)
// ---------------------------------------------------------------------------
#define TCHUNK 128

__global__ __launch_bounds__(256)
void conv_residual_kernel(const float* __restrict__ x,
                          const float* __restrict__ in_cache,
                          const float* __restrict__ conv_w,
                          float* __restrict__ m)
{
    const int p  = blockIdx.x * 256 + threadIdx.x;
    const int b  = blockIdx.z;
    const int t0 = blockIdx.y * TCHUNK;

    float w[LORD];
    #pragma unroll
    for (int l = 0; l < LORD; l++) w[l] = conv_w[p * LORD + l];

    float win[LORD - 1];
    #pragma unroll
    for (int i = 0; i < LORD - 1; i++) {
        const int j = t0 - (LORD - 1) + i;
        if (j >= 0)
            win[i] = x[((size_t)b * T_ + j) * DPRJ + p];
        else
            win[i] = in_cache[((size_t)b * DPRJ + p) * (LORD - 1) + (j + LORD - 1)];
    }

    const float* xrow = x + ((size_t)b * T_ + t0) * DPRJ + p;
    float*       mrow = m + ((size_t)b * T_ + t0) * DPRJ + p;

    for (int t = 0; t < TCHUNK; t++) {
        const float xv = xrow[(size_t)t * DPRJ];
        float acc = fmaf(w[LORD - 1], xv, xv);
        #pragma unroll
        for (int l = 0; l < LORD - 1; l++)
            acc = fmaf(w[l], win[l], acc);
        mrow[(size_t)t * DPRJ] = acc;
        #pragma unroll
        for (int i = 0; i < LORD - 2; i++) win[i] = win[i + 1];
        win[LORD - 2] = xv;
    }
}

__global__ void cache_kernel(const float* __restrict__ x,
                             float* __restrict__ out_cache)
{
    const int idx = blockIdx.x * blockDim.x + threadIdx.x;
    const int total = B_ * DPRJ * (LORD - 1);
    if (idx >= total) return;
    const int i = idx % (LORD - 1);
    const int p = (idx / (LORD - 1)) % DPRJ;
    const int b = idx / ((LORD - 1) * DPRJ);
    out_cache[idx] = x[((size_t)b * T_ + (T_ - (LORD - 1) + i)) * DPRJ + p];
}

// ---------------------------------------------------------------------------
extern "C" void kernel_launch(void* const* d_in, const int* in_sizes, int n_in,
                              void* d_out, int out_size)
{
    const float* input    = (const float*)d_in[0];  // [16, 2048, 1024]
    const float* in_cache = (const float*)d_in[1];  // [16, 512, 19]
    const float* W_lin    = (const float*)d_in[2];  // [1024, 512]
    const float* conv_w   = (const float*)d_in[3];  // [512, 20]
    const float* W_aff    = (const float*)d_in[4];  // [512, 1024]
    const float* b_aff    = (const float*)d_in[5];  // [1024]

    float* out       = (float*)d_out;
    float* out_cache = out + (size_t)B_ * T_ * DOUT;

    float *xbuf, *mbuf;
    __nv_bfloat16 *b1h, *b1l, *b2h, *b2l;
    cudaGetSymbolAddress((void**)&xbuf, g_x);
    cudaGetSymbolAddress((void**)&mbuf, g_m);
    cudaGetSymbolAddress((void**)&b1h, g_b1h);
    cudaGetSymbolAddress((void**)&b1l, g_b1l);
    cudaGetSymbolAddress((void**)&b2h, g_b2h);
    cudaGetSymbolAddress((void**)&b2l, g_b2l);

    const int SMEM_SZ = 2 * STG_BYTES;   // 81920 B
    cudaFuncSetAttribute(gemm_mma<false>, cudaFuncAttributeMaxDynamicSharedMemorySize, SMEM_SZ);
    cudaFuncSetAttribute(gemm_mma<true>,  cudaFuncAttributeMaxDynamicSharedMemorySize, SMEM_SZ);

    // 0) weight prep (transpose + hi/lo split)
    prep_w1<<<(DPRJ * DIN + 255) / 256, 256>>>(W_lin, b1h, b1l);
    prep_w2<<<(DOUT * DPRJ + 255) / 256, 256>>>(W_aff, b2h, b2l);

    // 1) x = input @ W_lin      M=32768, N=512, K=1024
    {
        dim3 grid(DPRJ / 128, MROWS / 128);
        gemm_mma<false><<<grid, 256, SMEM_SZ>>>(MROWS, DPRJ, DIN, input, b1h, b1l, nullptr, xbuf);
    }

    // 2) m = depthwise_conv(x) + x ; out_cache
    {
        dim3 grid(DPRJ / 256, T_ / TCHUNK, B_);
        conv_residual_kernel<<<grid, 256>>>(xbuf, in_cache, conv_w, mbuf);
        const int total = B_ * DPRJ * (LORD - 1);
        cache_kernel<<<(total + 255) / 256, 256>>>(xbuf, out_cache);
    }

    // 3) out = relu(m @ W_aff + b_aff)   M=32768, N=1024, K=512
    {
        dim3 grid(DOUT / 128, MROWS / 128);
        gemm_mma<true><<<grid, 256, SMEM_SZ>>>(MROWS, DOUT, DPRJ, mbuf, b2h, b2l, b_aff, out);
    }
}

// round 10
// speedup vs baseline: 2.0239x; 1.0366x over previous
#include <cuda_runtime.h>
#include <cuda_bf16.h>
#include <cstdint>

// Problem constants
#define B_   16
#define T_   2048
#define DIN  1024
#define DPRJ 512
#define DOUT 1024
#define LORD 20
#define MROWS (B_ * T_)          // 32768

// ---------------------------------------------------------------------------
// Device scratch (allocation-free)
// ---------------------------------------------------------------------------
__device__ float g_x[(size_t)MROWS * DPRJ];                 // x fp32 (conv in, out_cache)
__device__ __nv_bfloat16 g_a1h[(size_t)MROWS * DIN];        // input split hi
__device__ __nv_bfloat16 g_a1l[(size_t)MROWS * DIN];        // input split lo
__device__ __nv_bfloat16 g_mh[(size_t)MROWS * DPRJ];        // m split hi
__device__ __nv_bfloat16 g_ml[(size_t)MROWS * DPRJ];        // m split lo
// Transposed, split weights: rows = N dim, K contiguous
__device__ __nv_bfloat16 g_b1h[(size_t)DPRJ * DIN];         // [512][1024]
__device__ __nv_bfloat16 g_b1l[(size_t)DPRJ * DIN];
__device__ __nv_bfloat16 g_b2h[(size_t)DOUT * DPRJ];        // [1024][512]
__device__ __nv_bfloat16 g_b2l[(size_t)DOUT * DPRJ];

__device__ __forceinline__ float4 ld4(const float* p) {
    return *reinterpret_cast<const float4*>(p);
}

__device__ __forceinline__ uint32_t smem_u32(const void* p) {
    uint32_t a;
    asm("{ .reg .u64 t; cvta.to.shared.u64 t, %1; cvt.u32.u64 %0, t; }"
        : "=r"(a) : "l"(p));
    return a;
}

// cp.async 16B global -> shared
__device__ __forceinline__ void cp16(uint32_t dst, const void* src) {
    asm volatile("cp.async.cg.shared.global [%0], [%1], 16;"
                 :: "r"(dst), "l"(src));
}
#define CP_COMMIT() asm volatile("cp.async.commit_group;" ::: "memory")
template <int N>
__device__ __forceinline__ void cp_wait() {
    asm volatile("cp.async.wait_group %0;" :: "n"(N) : "memory");
}

// ldmatrix x4 (four 8x8 b16 matrices)
__device__ __forceinline__ void ldsm4(uint32_t* r, uint32_t addr) {
    asm volatile("ldmatrix.sync.aligned.m8n8.x4.shared.b16 {%0,%1,%2,%3}, [%4];"
                 : "=r"(r[0]), "=r"(r[1]), "=r"(r[2]), "=r"(r[3])
                 : "r"(addr));
}

// mma.sync m16n8k16 bf16 -> f32
__device__ __forceinline__ void mma_bf16(float* c, const uint32_t* a,
                                         uint32_t b0, uint32_t b1) {
    asm volatile(
        "mma.sync.aligned.m16n8k16.row.col.f32.bf16.bf16.f32 "
        "{%0,%1,%2,%3}, {%4,%5,%6,%7}, {%8,%9}, {%0,%1,%2,%3};"
        : "+f"(c[0]), "+f"(c[1]), "+f"(c[2]), "+f"(c[3])
        : "r"(a[0]), "r"(a[1]), "r"(a[2]), "r"(a[3]), "r"(b0), "r"(b1));
}

// ---------------------------------------------------------------------------
// Tensor-core GEMM via mma.sync: C[M,N] = A[M,K] * B^T (bf16 3-term split)
// All operands pre-split bf16 in GMEM. cp.async 3-stage pipeline.
// CTA 128x128, KC=32, 256 threads (8 warps, 2x4), warp tile 64x32.
// SMEM stage: Ah, Al, Bh, Bl each [128][40] bf16 (stride-40 padding).
// ---------------------------------------------------------------------------
#define KC        32
#define STR       40
#define TEN_BYTES (128 * STR * 2)         // 10240
#define STG_BYTES (4 * TEN_BYTES)         // 40960
#define STAGES    3

template <bool RELU>
__global__ __launch_bounds__(256)
void gemm_mma(int M, int N, int K,
              const __nv_bfloat16* __restrict__ Ahg_,
              const __nv_bfloat16* __restrict__ Alg_,
              const __nv_bfloat16* __restrict__ Bhg_,
              const __nv_bfloat16* __restrict__ Blg_,
              const float* __restrict__ bias,
              float* __restrict__ C)
{
    extern __shared__ char smem_raw[];
    const uint32_t sb = smem_u32(smem_raw);

    const int tid  = threadIdx.x;
    const int lane = tid & 31;
    const int wid  = tid >> 5;
    const int warpM = wid >> 2;           // 0..1
    const int warpN = wid & 3;            // 0..3
    const int nt = blockIdx.x;
    const int mt = blockIdx.y;
    const int NKC = K / KC;

    const __nv_bfloat16* Ahg = Ahg_ + (size_t)mt * 128 * K;
    const __nv_bfloat16* Alg = Alg_ + (size_t)mt * 128 * K;
    const __nv_bfloat16* Bhg = Bhg_ + (size_t)nt * 128 * K;
    const __nv_bfloat16* Blg = Blg_ + (size_t)nt * 128 * K;

    float acc[4][4][4];
    #pragma unroll
    for (int i = 0; i < 4; i++)
        #pragma unroll
        for (int j = 0; j < 4; j++)
            #pragma unroll
            for (int q = 0; q < 4; q++) acc[i][j][q] = 0.f;

    // per-thread cp.async coordinates: 2 chunks of 16B per tensor
    // chunk i in 0..511: row r = i>>2 (0..127), c8 = i&3 (k = c8*8)
    const int r0  = tid >> 2,  c80  = tid & 3;
    const int r1  = (tid + 256) >> 2, c81 = (tid + 256) & 3;
    const uint32_t so0 = (uint32_t)(r0 * 80 + c80 * 16);
    const uint32_t so1 = (uint32_t)(r1 * 80 + c81 * 16);

    auto issue = [&](int slot, int kc) {
        const uint32_t st = sb + slot * STG_BYTES;
        const size_t g0 = (size_t)r0 * K + kc * KC + c80 * 8;
        const size_t g1 = (size_t)r1 * K + kc * KC + c81 * 8;
        cp16(st + so0,                 Ahg + g0);
        cp16(st + so1,                 Ahg + g1);
        cp16(st + TEN_BYTES + so0,     Alg + g0);
        cp16(st + TEN_BYTES + so1,     Alg + g1);
        cp16(st + 2 * TEN_BYTES + so0, Bhg + g0);
        cp16(st + 2 * TEN_BYTES + so1, Bhg + g1);
        cp16(st + 3 * TEN_BYTES + so0, Blg + g0);
        cp16(st + 3 * TEN_BYTES + so1, Blg + g1);
        CP_COMMIT();
    };

    const int lr = lane & 15;
    const int lc = lane >> 4;

    auto compute = [&](int slot) {
        const uint32_t sAh = sb + slot * STG_BYTES;
        const uint32_t sAl = sAh + TEN_BYTES;
        const uint32_t sBh = sAh + 2 * TEN_BYTES;
        const uint32_t sBl = sAh + 3 * TEN_BYTES;
        #pragma unroll
        for (int ks = 0; ks < KC; ks += 16) {
            uint32_t ah[4][4], al[4][4], bh[2][4], bl[2][4];
            #pragma unroll
            for (int i = 0; i < 4; i++) {
                const uint32_t ao =
                    ((warpM * 64 + i * 16 + lr) * STR + ks + lc * 8) * 2;
                ldsm4(ah[i], sAh + ao);
                ldsm4(al[i], sAl + ao);
            }
            #pragma unroll
            for (int jj = 0; jj < 2; jj++) {
                const uint32_t bo =
                    ((warpN * 32 + jj * 16 + lr) * STR + ks + lc * 8) * 2;
                ldsm4(bh[jj], sBh + bo);
                ldsm4(bl[jj], sBl + bo);
            }
            #pragma unroll
            for (int i = 0; i < 4; i++) {
                #pragma unroll
                for (int j = 0; j < 4; j++) {
                    const int jj = j >> 1, sel = j & 1;
                    const uint32_t b0h = bh[jj][sel], b1h = bh[jj][sel + 2];
                    mma_bf16(acc[i][j], ah[i], b0h, b1h);                       // Ah*Bh
                    mma_bf16(acc[i][j], al[i], b0h, b1h);                       // Al*Bh
                    mma_bf16(acc[i][j], ah[i], bl[jj][sel], bl[jj][sel + 2]);   // Ah*Bl
                }
            }
        }
    };

    // ---- 3-stage cp.async pipeline, one sync per chunk ----
    issue(0, 0);
    issue(1, 1);
    for (int kc = 0; kc < NKC; kc++) {
        cp_wait<STAGES - 2>();
        __syncthreads();                      // stage kc%3 ready; stage (kc+2)%3 free
        const int nk = kc + STAGES - 1;
        if (nk < NKC) issue(nk % STAGES, nk); // overlaps with compute below
        compute(kc % STAGES);
    }

    // ---- epilogue ----
    #pragma unroll
    for (int i = 0; i < 4; i++) {
        const int row0 = mt * 128 + warpM * 64 + i * 16 + (lane >> 2);
        #pragma unroll
        for (int j = 0; j < 4; j++) {
            const int col = nt * 128 + warpN * 32 + j * 8 + (lane & 3) * 2;
            float2 v0, v1;
            v0.x = acc[i][j][0]; v0.y = acc[i][j][1];   // row0
            v1.x = acc[i][j][2]; v1.y = acc[i][j][3];   // row0 + 8
            if (RELU) {
                const float b0 = bias[col], b1 = bias[col + 1];
                v0.x = fmaxf(v0.x + b0, 0.f); v0.y = fmaxf(v0.y + b1, 0.f);
                v1.x = fmaxf(v1.x + b0, 0.f); v1.y = fmaxf(v1.y + b1, 0.f);
            }
            *reinterpret_cast<float2*>(C + (size_t)row0 * N + col)       = v0;
            *reinterpret_cast<float2*>(C + (size_t)(row0 + 8) * N + col) = v1;
        }
    }
}

// ---------------------------------------------------------------------------
// Input pre-split: fp32 -> bf16 hi/lo (vectorized)
// ---------------------------------------------------------------------------
__global__ void split_input(const float* __restrict__ in,
                            __nv_bfloat16* __restrict__ h,
                            __nv_bfloat16* __restrict__ l)
{
    const size_t i4 = (size_t)blockIdx.x * 256 + threadIdx.x;  // float4 index
    const float4 v = ld4(in + i4 * 4);
    __nv_bfloat16 hx = __float2bfloat16(v.x);
    __nv_bfloat16 hy = __float2bfloat16(v.y);
    __nv_bfloat16 hz = __float2bfloat16(v.z);
    __nv_bfloat16 hw = __float2bfloat16(v.w);
    __nv_bfloat16 lx = __float2bfloat16(v.x - __bfloat162float(hx));
    __nv_bfloat16 ly = __float2bfloat16(v.y - __bfloat162float(hy));
    __nv_bfloat16 lz = __float2bfloat16(v.z - __bfloat162float(hz));
    __nv_bfloat16 lw = __float2bfloat16(v.w - __bfloat162float(hw));
    uint2 hv, lv;
    hv.x = (uint32_t)__bfloat16_as_ushort(hx) | ((uint32_t)__bfloat16_as_ushort(hy) << 16);
    hv.y = (uint32_t)__bfloat16_as_ushort(hz) | ((uint32_t)__bfloat16_as_ushort(hw) << 16);
    lv.x = (uint32_t)__bfloat16_as_ushort(lx) | ((uint32_t)__bfloat16_as_ushort(ly) << 16);
    lv.y = (uint32_t)__bfloat16_as_ushort(lz) | ((uint32_t)__bfloat16_as_ushort(lw) << 16);
    *reinterpret_cast<uint2*>(h + i4 * 4) = hv;
    *reinterpret_cast<uint2*>(l + i4 * 4) = lv;
}

// ---------------------------------------------------------------------------
// Weight prep: transpose + bf16 hi/lo split
// ---------------------------------------------------------------------------
__global__ void prep_w1(const float* __restrict__ W,   // W_lin [1024,512]
                        __nv_bfloat16* __restrict__ bh,
                        __nv_bfloat16* __restrict__ bl)
{
    const int idx = blockIdx.x * 256 + threadIdx.x;
    if (idx >= DPRJ * DIN) return;
    const int n = idx / DIN, k = idx % DIN;
    const float v = W[(size_t)k * DPRJ + n];
    const __nv_bfloat16 h = __float2bfloat16(v);
    bh[idx] = h;
    bl[idx] = __float2bfloat16(v - __bfloat162float(h));
}

__global__ void prep_w2(const float* __restrict__ W,   // W_aff [512,1024]
                        __nv_bfloat16* __restrict__ bh,
                        __nv_bfloat16* __restrict__ bl)
{
    const int idx = blockIdx.x * 256 + threadIdx.x;
    if (idx >= DOUT * DPRJ) return;
    const int o = idx / DPRJ, p = idx % DPRJ;
    const float v = W[(size_t)p * DOUT + o];
    const __nv_bfloat16 h = __float2bfloat16(v);
    bh[idx] = h;
    bl[idx] = __float2bfloat16(v - __bfloat162float(h));
}

// ---------------------------------------------------------------------------
// Depthwise causal conv (L=20) + residual; emits m as bf16 hi/lo directly
// ---------------------------------------------------------------------------
#define TCHUNK 128

__global__ __launch_bounds__(256)
void conv_residual_kernel(const float* __restrict__ x,
                          const float* __restrict__ in_cache,
                          const float* __restrict__ conv_w,
                          __nv_bfloat16* __restrict__ mh,
                          __nv_bfloat16* __restrict__ ml)
{
    const int p  = blockIdx.x * 256 + threadIdx.x;
    const int b  = blockIdx.z;
    const int t0 = blockIdx.y * TCHUNK;

    float w[LORD];
    #pragma unroll
    for (int l = 0; l < LORD; l++) w[l] = conv_w[p * LORD + l];

    float win[LORD - 1];
    #pragma unroll
    for (int i = 0; i < LORD - 1; i++) {
        const int j = t0 - (LORD - 1) + i;
        if (j >= 0)
            win[i] = x[((size_t)b * T_ + j) * DPRJ + p];
        else
            win[i] = in_cache[((size_t)b * DPRJ + p) * (LORD - 1) + (j + LORD - 1)];
    }

    const float* xrow = x  + ((size_t)b * T_ + t0) * DPRJ + p;
    __nv_bfloat16* mhrow = mh + ((size_t)b * T_ + t0) * DPRJ + p;
    __nv_bfloat16* mlrow = ml + ((size_t)b * T_ + t0) * DPRJ + p;

    for (int t = 0; t < TCHUNK; t++) {
        const float xv = xrow[(size_t)t * DPRJ];
        float acc = fmaf(w[LORD - 1], xv, xv);
        #pragma unroll
        for (int l = 0; l < LORD - 1; l++)
            acc = fmaf(w[l], win[l], acc);
        const __nv_bfloat16 h = __float2bfloat16(acc);
        mhrow[(size_t)t * DPRJ] = h;
        mlrow[(size_t)t * DPRJ] = __float2bfloat16(acc - __bfloat162float(h));
        #pragma unroll
        for (int i = 0; i < LORD - 2; i++) win[i] = win[i + 1];
        win[LORD - 2] = xv;
    }
}

__global__ void cache_kernel(const float* __restrict__ x,
                             float* __restrict__ out_cache)
{
    const int idx = blockIdx.x * blockDim.x + threadIdx.x;
    const int total = B_ * DPRJ * (LORD - 1);
    if (idx >= total) return;
    const int i = idx % (LORD - 1);
    const int p = (idx / (LORD - 1)) % DPRJ;
    const int b = idx / ((LORD - 1) * DPRJ);
    out_cache[idx] = x[((size_t)b * T_ + (T_ - (LORD - 1) + i)) * DPRJ + p];
}

// ---------------------------------------------------------------------------
extern "C" void kernel_launch(void* const* d_in, const int* in_sizes, int n_in,
                              void* d_out, int out_size)
{
    const float* input    = (const float*)d_in[0];  // [16, 2048, 1024]
    const float* in_cache = (const float*)d_in[1];  // [16, 512, 19]
    const float* W_lin    = (const float*)d_in[2];  // [1024, 512]
    const float* conv_w   = (const float*)d_in[3];  // [512, 20]
    const float* W_aff    = (const float*)d_in[4];  // [512, 1024]
    const float* b_aff    = (const float*)d_in[5];  // [1024]

    float* out       = (float*)d_out;
    float* out_cache = out + (size_t)B_ * T_ * DOUT;

    float *xbuf;
    __nv_bfloat16 *a1h, *a1l, *mh, *ml, *b1h, *b1l, *b2h, *b2l;
    cudaGetSymbolAddress((void**)&xbuf, g_x);
    cudaGetSymbolAddress((void**)&a1h, g_a1h);
    cudaGetSymbolAddress((void**)&a1l, g_a1l);
    cudaGetSymbolAddress((void**)&mh,  g_mh);
    cudaGetSymbolAddress((void**)&ml,  g_ml);
    cudaGetSymbolAddress((void**)&b1h, g_b1h);
    cudaGetSymbolAddress((void**)&b1l, g_b1l);
    cudaGetSymbolAddress((void**)&b2h, g_b2h);
    cudaGetSymbolAddress((void**)&b2l, g_b2l);

    const int SMEM_SZ = STAGES * STG_BYTES;   // 122880 B
    cudaFuncSetAttribute(gemm_mma<false>, cudaFuncAttributeMaxDynamicSharedMemorySize, SMEM_SZ);
    cudaFuncSetAttribute(gemm_mma<true>,  cudaFuncAttributeMaxDynamicSharedMemorySize, SMEM_SZ);

    // 0) operand prep: input split + weight transpose/split
    split_input<<<(MROWS * (size_t)DIN / 4 + 255) / 256, 256>>>(input, a1h, a1l);
    prep_w1<<<(DPRJ * DIN + 255) / 256, 256>>>(W_lin, b1h, b1l);
    prep_w2<<<(DOUT * DPRJ + 255) / 256, 256>>>(W_aff, b2h, b2l);

    // 1) x = input @ W_lin      M=32768, N=512, K=1024
    {
        dim3 grid(DPRJ / 128, MROWS / 128);
        gemm_mma<false><<<grid, 256, SMEM_SZ>>>(MROWS, DPRJ, DIN,
                                                a1h, a1l, b1h, b1l, nullptr, xbuf);
    }

    // 2) m = depthwise_conv(x) + x  (bf16 split out) ; out_cache
    {
        dim3 grid(DPRJ / 256, T_ / TCHUNK, B_);
        conv_residual_kernel<<<grid, 256>>>(xbuf, in_cache, conv_w, mh, ml);
        const int total = B_ * DPRJ * (LORD - 1);
        cache_kernel<<<(total + 255) / 256, 256>>>(xbuf, out_cache);
    }

    // 3) out = relu(m @ W_aff + b_aff)   M=32768, N=1024, K=512
    {
        dim3 grid(DOUT / 128, MROWS / 128);
        gemm_mma<true><<<grid, 256, SMEM_SZ>>>(MROWS, DOUT, DPRJ,
                                               mh, ml, b2h, b2l, b_aff, out);
    }
}